// round 13
// baseline (speedup 1.0000x reference)
#include <cuda_runtime.h>
#include <cuda_fp16.h>
#include <cstdint>

// ============================================================
// Problem constants
// ============================================================
#define NUM_E     8
#define DIM_H     1024
#define DIM_F     4096
#define TOK_TOTAL 16384
#define TOK_PER_E 2048

// GEMM tiling: CTA 128x256, 8 warps of 64x64, 3-stage pipeline, 1 CTA/SM
#define STAGES  3
#define KT      64             // k halves per stage (= 128 bytes/row)
#define MT      128
#define NT      256

#define A_STRIDE_H      72     // halves per smem row (64 data + 8 pad = 144B) -> conflict-free
#define ROW_B           144    // row bytes
#define A_STAGE_HALFS   (MT * A_STRIDE_H)        // 9216
#define B_STAGE_HALFS   (NT * A_STRIDE_H)        // 18432
#define STAGE_HALFS     (A_STAGE_HALFS + B_STAGE_HALFS)
#define STAGE_BYTES     (STAGE_HALFS * 2)        // 55296
#define A_STAGE_BYTES   (A_STAGE_HALFS * 2)      // 18432
#define SMEM_ALLOC      (STAGES * STAGE_BYTES)   // 165888 bytes

// ============================================================
// Scratch (__device__ globals — allocation-free rule)
// ============================================================
__device__ __half g_xh[(size_t)TOK_TOTAL * DIM_H];         //  32 MB  x (fp16)
__device__ __half g_w1t[(size_t)NUM_E * DIM_F * DIM_H];    //  64 MB  w1^T [e][f][h] fp16
__device__ __half g_w2t[(size_t)NUM_E * DIM_H * DIM_F];    //  64 MB  w2^T [e][h][f] fp16
__device__ __half g_inter[(size_t)TOK_TOTAL * DIM_F];      // 128 MB  gelu(x@w1) fp16

// ============================================================
// Helpers (baseline PTX only — no tcgen05 on this toolchain)
// ============================================================
__device__ __forceinline__ uint32_t smem_to_u32(const void* smem_ptr) {
    uint32_t addr;
    asm("{ .reg .u64 tmp; cvta.to.shared.u64 tmp, %1; cvt.u32.u64 %0, tmp; }"
        : "=r"(addr) : "l"(smem_ptr));
    return addr;
}

__device__ __forceinline__ void cp_async16(uint32_t smem_addr, const void* gptr) {
    asm volatile("cp.async.cg.shared.global [%0], [%1], 16;"
                 :: "r"(smem_addr), "l"(gptr));
}
#define CP_ASYNC_COMMIT() asm volatile("cp.async.commit_group;" ::: "memory")
template <int N>
__device__ __forceinline__ void cp_async_wait_group() {
    asm volatile("cp.async.wait_group %0;" :: "n"(N) : "memory");
}

// ldmatrix x4: four 8x8 b16 tiles
__device__ __forceinline__ void ldsm_x4(uint32_t (&d)[4], uint32_t addr) {
    asm volatile("ldmatrix.sync.aligned.m8n8.x4.shared.b16 {%0,%1,%2,%3}, [%4];"
                 : "=r"(d[0]), "=r"(d[1]), "=r"(d[2]), "=r"(d[3]) : "r"(addr));
}

// mma.sync m16n8k16 fp16 -> f32 accumulate (sm_80+ baseline PTX)
__device__ __forceinline__ void mma_f16(float (&d)[4],
                                        const uint32_t (&a)[4],
                                        uint32_t b0, uint32_t b1) {
    asm volatile(
        "mma.sync.aligned.m16n8k16.row.col.f32.f16.f16.f32 "
        "{%0,%1,%2,%3}, {%4,%5,%6,%7}, {%8,%9}, {%0,%1,%2,%3};"
        : "+f"(d[0]), "+f"(d[1]), "+f"(d[2]), "+f"(d[3])
        : "r"(a[0]), "r"(a[1]), "r"(a[2]), "r"(a[3]),
          "r"(b0), "r"(b1));
}

__device__ __forceinline__ float gelu_tanh(float x) {
    float x3 = x * x * x;
    float t  = tanhf(0.7978845608028654f * (x + 0.044715f * x3));
    return 0.5f * x * (1.0f + t);
}

// ============================================================
// Prep kernels: fp32 -> fp16 (RN), plus K-major transposes
// ============================================================
__global__ void convert_h_kernel(const float* __restrict__ in, __half* __restrict__ out, int n)
{
    for (int i = blockIdx.x * blockDim.x + threadIdx.x; i < n; i += gridDim.x * blockDim.x)
        out[i] = __float2half_rn(in[i]);
}

// in: [E][R][C] fp32 -> out: [E][C][R] fp16
__global__ void transpose_h_kernel(const float* __restrict__ in, __half* __restrict__ out,
                                   int R, int C)
{
    __shared__ float tile[32][33];
    const int e  = blockIdx.z;
    const int c0 = blockIdx.x << 5;
    const int r0 = blockIdx.y << 5;
    const float* ine  = in  + (size_t)e * R * C;
    __half*      oute = out + (size_t)e * R * C;
    const int tx = threadIdx.x, ty = threadIdx.y;   // 32 x 8
#pragma unroll
    for (int dy = 0; dy < 32; dy += 8)
        tile[ty + dy][tx] = ine[(size_t)(r0 + ty + dy) * C + c0 + tx];
    __syncthreads();
#pragma unroll
    for (int dy = 0; dy < 32; dy += 8)
        oute[(size_t)(c0 + ty + dy) * R + r0 + tx] = __float2half_rn(tile[tx][ty + dy]);
}

// ============================================================
// Grouped fp16 GEMM:  C[e] (+gelu) = A[e] @ B[e]^T
//   A: [Mtot, K] K-major fp16;  B: [Ntot, K] K-major fp16
//   C: fp16 (when do_gelu, -> inter) or fp32 (final output)
// CTA: 128x256, 8 warps of 64x64, KT=64, 3-stage cp.async, 1 CTA/SM,
// ldmatrix.x4 fragment loads.
// ============================================================
__global__ void __launch_bounds__(256, 1) gemm_f16_kernel(
    const __half* __restrict__ A, int lda, long sAe,
    const __half* __restrict__ B, int ldb, long sBe,
    void* __restrict__ Cv, int ldc, long sCe,
    int K, int n_tiles, int do_gelu)
{
    extern __shared__ __half smemh[];
    const uint32_t smem_base = smem_to_u32(smemh);

    const int tid = threadIdx.x;
    const int wid = tid >> 5;
    const int lid = tid & 31;
    const int g   = lid >> 2;      // groupID (0..7)
    const int tig = lid & 3;       // thread in group (0..3)
    const int wm  = (wid & 1) * 64;      // 2 warps across M
    const int wn  = (wid >> 1) * 64;     // 4 warps across N

    const int e  = blockIdx.y;
    const int mt = blockIdx.x / n_tiles;
    const int nt = blockIdx.x - mt * n_tiles;

    const __half* Ab = A + (size_t)e * sAe + (size_t)mt * MT * lda;
    const __half* Bb = B + (size_t)e * sBe + (size_t)nt * NT * ldb;

    float acc[4][8][4];                  // [mfrag][nfrag][quad]
#pragma unroll
    for (int f = 0; f < 4; f++)
#pragma unroll
        for (int j = 0; j < 8; j++)
#pragma unroll
            for (int q = 0; q < 4; q++) acc[f][j][q] = 0.0f;

    // per-lane ldmatrix offsets (bytes, within a stage buffer):
    // A x4 tiles: [r0-7,k0-7],[r8-15,k0-7],[r0-7,k8-15],[r8-15,k8-15]
    const uint32_t a_loff = (uint32_t)(wm * ROW_B + (lid & 15) * ROW_B + (lid >> 4) * 16);
    // B x4 tiles: [n0-7,k0-7],[n0-7,k8-15],[n8-15,k0-7],[n8-15,k8-15]
    const uint32_t b_loff = (uint32_t)(A_STAGE_BYTES + wn * ROW_B + (lid & 7) * ROW_B
                                       + ((lid >> 3) & 1) * 16 + (lid >> 4) * (8 * ROW_B));

    // ---------------- stage loader ----------------
    // A: 128 rows x 8 chunks = 1024 (4/thread); B: 256 rows = 2048 (8/thread)
    auto load_stage = [&](int buf, int k0) {
        __half* as_ = smemh + buf * STAGE_HALFS;
#pragma unroll
        for (int t = 0; t < 4; t++) {
            int idx = tid + t * 256;
            int r = idx >> 3, c = idx & 7;
            cp_async16(smem_to_u32(as_ + r * A_STRIDE_H + c * 8),
                       Ab + (size_t)r * lda + k0 + c * 8);
        }
        __half* bs_ = as_ + A_STAGE_HALFS;
#pragma unroll
        for (int t = 0; t < 8; t++) {
            int idx = tid + t * 256;
            int r = idx >> 3, c = idx & 7;
            cp_async16(smem_to_u32(bs_ + r * A_STRIDE_H + c * 8),
                       Bb + (size_t)r * ldb + k0 + c * 8);
        }
    };

    const int NK = K / KT;

    // prologue: fill stages 0..STAGES-2
#pragma unroll
    for (int s = 0; s < STAGES - 1; s++) {
        load_stage(s, s * KT);
        CP_ASYNC_COMMIT();
    }

    int buf = 0;
    for (int i = 0; i < NK; i++) {
        cp_async_wait_group<STAGES - 2>();
        __syncthreads();

        // issue next stage's loads into the buffer consumed last iteration
        const int jn = i + STAGES - 1;
        int nbuf = buf + 1; if (nbuf == STAGES) nbuf = 0;
        if (jn < NK) {
            int lbuf = buf - 1; if (lbuf < 0) lbuf += STAGES;
            load_stage(lbuf, jn * KT);
        }
        CP_ASYNC_COMMIT();

        // compute on stage `buf`: 4 k-slices of k16, LDSM fragment loads
        const uint32_t sa = smem_base + buf * STAGE_BYTES;
#pragma unroll
        for (int kk = 0; kk < KT / 16; kk++) {
            const uint32_t koff = sa + kk * 32;
            uint32_t a[4][4];
#pragma unroll
            for (int f = 0; f < 4; f++)
                ldsm_x4(a[f], koff + a_loff + f * (16 * ROW_B));
            uint32_t bb[4][4];   // bb[p] = {j(2p).b0, j(2p).b1, j(2p+1).b0, j(2p+1).b1}
#pragma unroll
            for (int p = 0; p < 4; p++)
                ldsm_x4(bb[p], koff + b_loff + p * (16 * ROW_B));
#pragma unroll
            for (int f = 0; f < 4; f++)
#pragma unroll
                for (int j = 0; j < 8; j++)
                    mma_f16(acc[f][j], a[f],
                            bb[j >> 1][(j & 1) * 2], bb[j >> 1][(j & 1) * 2 + 1]);
        }
        buf = nbuf;
    }

    // ---------------- epilogue ----------------
    if (do_gelu) {
        __half* Cb = (__half*)Cv + (size_t)e * sCe + (size_t)mt * MT * ldc + (size_t)nt * NT;
#pragma unroll
        for (int f = 0; f < 4; f++) {
            const int r0 = wm + 16 * f + g;
            const int r1 = r0 + 8;
#pragma unroll
            for (int j = 0; j < 8; j++) {
                const int col = wn + 8 * j + 2 * tig;
                __half2 p0 = __floats2half2_rn(gelu_tanh(acc[f][j][0]),
                                               gelu_tanh(acc[f][j][1]));
                __half2 p1 = __floats2half2_rn(gelu_tanh(acc[f][j][2]),
                                               gelu_tanh(acc[f][j][3]));
                *reinterpret_cast<__half2*>(Cb + (size_t)r0 * ldc + col) = p0;
                *reinterpret_cast<__half2*>(Cb + (size_t)r1 * ldc + col) = p1;
            }
        }
    } else {
        float* Cb = (float*)Cv + (size_t)e * sCe + (size_t)mt * MT * ldc + (size_t)nt * NT;
#pragma unroll
        for (int f = 0; f < 4; f++) {
            const int r0 = wm + 16 * f + g;
            const int r1 = r0 + 8;
#pragma unroll
            for (int j = 0; j < 8; j++) {
                const int col = wn + 8 * j + 2 * tig;
                *reinterpret_cast<float2*>(Cb + (size_t)r0 * ldc + col) =
                    make_float2(acc[f][j][0], acc[f][j][1]);
                *reinterpret_cast<float2*>(Cb + (size_t)r1 * ldc + col) =
                    make_float2(acc[f][j][2], acc[f][j][3]);
            }
        }
    }
}

// ============================================================
// Host launcher
// ============================================================
extern "C" void kernel_launch(void* const* d_in, const int* in_sizes, int n_in,
                              void* d_out, int out_size)
{
    const float* x  = (const float*)d_in[0];
    const float* w1 = (const float*)d_in[1];
    const float* w2 = (const float*)d_in[2];
    float* out = (float*)d_out;

    __half *xh, *w1t, *w2t, *inter;
    cudaGetSymbolAddress((void**)&xh,    g_xh);
    cudaGetSymbolAddress((void**)&w1t,   g_w1t);
    cudaGetSymbolAddress((void**)&w2t,   g_w2t);
    cudaGetSymbolAddress((void**)&inter, g_inter);

    cudaFuncSetAttribute(gemm_f16_kernel,
                         cudaFuncAttributeMaxDynamicSharedMemorySize, SMEM_ALLOC);

    // prep: fp16 conversion + weight transposes to K-major
    convert_h_kernel<<<2048, 256>>>(x, xh, TOK_TOTAL * DIM_H);
    transpose_h_kernel<<<dim3(DIM_F / 32, DIM_H / 32, NUM_E), dim3(32, 8)>>>(
        w1, w1t, DIM_H, DIM_F);   // [E][H][F] -> [E][F][H]
    transpose_h_kernel<<<dim3(DIM_H / 32, DIM_F / 32, NUM_E), dim3(32, 8)>>>(
        w2, w2t, DIM_F, DIM_H);   // [E][F][H] -> [E][H][F]

    // GEMM1: inter = gelu(x @ w1^T_kmajor)   (M=2048/expert, N=4096, K=1024), fp16 out
    gemm_f16_kernel<<<dim3((TOK_PER_E / MT) * (DIM_F / NT), NUM_E), 256, SMEM_ALLOC>>>(
        xh,    DIM_H, (long)TOK_PER_E * DIM_H,
        w1t,   DIM_H, (long)DIM_F * DIM_H,
        inter, DIM_F, (long)TOK_PER_E * DIM_F,
        DIM_H, DIM_F / NT, /*gelu=*/1);

    // GEMM2: out = inter @ w2^T_kmajor       (M=2048/expert, N=1024, K=4096), fp32 out
    gemm_f16_kernel<<<dim3((TOK_PER_E / MT) * (DIM_H / NT), NUM_E), 256, SMEM_ALLOC>>>(
        inter, DIM_F, (long)TOK_PER_E * DIM_F,
        w2t,   DIM_F, (long)DIM_H * DIM_F,
        out,   DIM_H, (long)TOK_PER_E * DIM_H,
        DIM_F, DIM_H / NT, /*gelu=*/0);
}

// round 14
// speedup vs baseline: 1.0654x; 1.0654x over previous
#include <cuda_runtime.h>
#include <cuda_fp16.h>
#include <cstdint>

// ============================================================
// Problem constants
// ============================================================
#define NUM_E     8
#define DIM_H     1024
#define DIM_F     4096
#define TOK_TOTAL 16384
#define TOK_PER_E 2048

// GEMM tiling: CTA 128x128, 4 warps of 64x64, 3-stage pipeline, 2 CTA/SM
#define STAGES  3
#define KT      64             // k halves per stage (= 128 bytes/row)
#define MT      128
#define NT      128
#define NTHR    128

#define A_STRIDE_H      72     // halves per smem row (64 data + 8 pad = 144B) -> conflict-free
#define ROW_B           144    // row bytes
#define A_STAGE_HALFS   (MT * A_STRIDE_H)        // 9216
#define B_STAGE_HALFS   (NT * A_STRIDE_H)        // 9216
#define STAGE_HALFS     (A_STAGE_HALFS + B_STAGE_HALFS)
#define STAGE_BYTES     (STAGE_HALFS * 2)        // 36864
#define A_STAGE_BYTES   (A_STAGE_HALFS * 2)      // 18432
#define SMEM_ALLOC      (STAGES * STAGE_BYTES)   // 110592 bytes

// ============================================================
// Scratch (__device__ globals — allocation-free rule)
// ============================================================
__device__ __half g_xh[(size_t)TOK_TOTAL * DIM_H];         //  32 MB  x (fp16)
__device__ __half g_w1t[(size_t)NUM_E * DIM_F * DIM_H];    //  64 MB  w1^T [e][f][h] fp16
__device__ __half g_w2t[(size_t)NUM_E * DIM_H * DIM_F];    //  64 MB  w2^T [e][h][f] fp16
__device__ __half g_inter[(size_t)TOK_TOTAL * DIM_F];      // 128 MB  gelu(x@w1) fp16

// ============================================================
// Helpers (baseline PTX only — no tcgen05 on this toolchain)
// ============================================================
__device__ __forceinline__ uint32_t smem_to_u32(const void* smem_ptr) {
    uint32_t addr;
    asm("{ .reg .u64 tmp; cvta.to.shared.u64 tmp, %1; cvt.u32.u64 %0, tmp; }"
        : "=r"(addr) : "l"(smem_ptr));
    return addr;
}

__device__ __forceinline__ void cp_async16(uint32_t smem_addr, const void* gptr) {
    asm volatile("cp.async.cg.shared.global [%0], [%1], 16;"
                 :: "r"(smem_addr), "l"(gptr));
}
#define CP_ASYNC_COMMIT() asm volatile("cp.async.commit_group;" ::: "memory")
template <int N>
__device__ __forceinline__ void cp_async_wait_group() {
    asm volatile("cp.async.wait_group %0;" :: "n"(N) : "memory");
}

// ldmatrix x4: four 8x8 b16 tiles
__device__ __forceinline__ void ldsm_x4(uint32_t (&d)[4], uint32_t addr) {
    asm volatile("ldmatrix.sync.aligned.m8n8.x4.shared.b16 {%0,%1,%2,%3}, [%4];"
                 : "=r"(d[0]), "=r"(d[1]), "=r"(d[2]), "=r"(d[3]) : "r"(addr));
}

// mma.sync m16n8k16 fp16 -> f32 accumulate (sm_80+ baseline PTX)
__device__ __forceinline__ void mma_f16(float (&d)[4],
                                        const uint32_t (&a)[4],
                                        uint32_t b0, uint32_t b1) {
    asm volatile(
        "mma.sync.aligned.m16n8k16.row.col.f32.f16.f16.f32 "
        "{%0,%1,%2,%3}, {%4,%5,%6,%7}, {%8,%9}, {%0,%1,%2,%3};"
        : "+f"(d[0]), "+f"(d[1]), "+f"(d[2]), "+f"(d[3])
        : "r"(a[0]), "r"(a[1]), "r"(a[2]), "r"(a[3]),
          "r"(b0), "r"(b1));
}

__device__ __forceinline__ float gelu_tanh(float x) {
    float x3 = x * x * x;
    float t  = tanhf(0.7978845608028654f * (x + 0.044715f * x3));
    return 0.5f * x * (1.0f + t);
}

// ============================================================
// Prep kernels: fp32 -> fp16 (RN), plus K-major transposes
// ============================================================
__global__ void convert_h_kernel(const float* __restrict__ in, __half* __restrict__ out, int n)
{
    for (int i = blockIdx.x * blockDim.x + threadIdx.x; i < n; i += gridDim.x * blockDim.x)
        out[i] = __float2half_rn(in[i]);
}

// in: [E][R][C] fp32 -> out: [E][C][R] fp16
__global__ void transpose_h_kernel(const float* __restrict__ in, __half* __restrict__ out,
                                   int R, int C)
{
    __shared__ float tile[32][33];
    const int e  = blockIdx.z;
    const int c0 = blockIdx.x << 5;
    const int r0 = blockIdx.y << 5;
    const float* ine  = in  + (size_t)e * R * C;
    __half*      oute = out + (size_t)e * R * C;
    const int tx = threadIdx.x, ty = threadIdx.y;   // 32 x 8
#pragma unroll
    for (int dy = 0; dy < 32; dy += 8)
        tile[ty + dy][tx] = ine[(size_t)(r0 + ty + dy) * C + c0 + tx];
    __syncthreads();
#pragma unroll
    for (int dy = 0; dy < 32; dy += 8)
        oute[(size_t)(c0 + ty + dy) * R + r0 + tx] = __float2half_rn(tile[tx][ty + dy]);
}

// ============================================================
// Grouped fp16 GEMM:  C[e] (+gelu) = A[e] @ B[e]^T
//   A: [Mtot, K] K-major fp16;  B: [Ntot, K] K-major fp16
//   C: fp16 (when do_gelu, -> inter) or fp32 (final output)
// CTA: 128x128, 4 warps of 64x64, KT=64, 3-stage cp.async, 2 CTA/SM,
// ldmatrix.x4 fragment loads. Decoupled barrier domains across the 2 CTAs.
// ============================================================
__global__ void __launch_bounds__(NTHR, 2) gemm_f16_kernel(
    const __half* __restrict__ A, int lda, long sAe,
    const __half* __restrict__ B, int ldb, long sBe,
    void* __restrict__ Cv, int ldc, long sCe,
    int K, int n_tiles, int do_gelu)
{
    extern __shared__ __half smemh[];
    const uint32_t smem_base = smem_to_u32(smemh);

    const int tid = threadIdx.x;
    const int wid = tid >> 5;
    const int lid = tid & 31;
    const int g   = lid >> 2;      // groupID (0..7)
    const int tig = lid & 3;       // thread in group (0..3)
    const int wm  = (wid & 1) * 64;      // 2 warps across M
    const int wn  = (wid >> 1) * 64;     // 2 warps across N

    const int e  = blockIdx.y;
    const int mt = blockIdx.x / n_tiles;
    const int nt = blockIdx.x - mt * n_tiles;

    const __half* Ab = A + (size_t)e * sAe + (size_t)mt * MT * lda;
    const __half* Bb = B + (size_t)e * sBe + (size_t)nt * NT * ldb;

    float acc[4][8][4];                  // [mfrag][nfrag][quad]
#pragma unroll
    for (int f = 0; f < 4; f++)
#pragma unroll
        for (int j = 0; j < 8; j++)
#pragma unroll
            for (int q = 0; q < 4; q++) acc[f][j][q] = 0.0f;

    // per-lane ldmatrix offsets (bytes, within a stage buffer):
    // A x4 tiles: [r0-7,k0-7],[r8-15,k0-7],[r0-7,k8-15],[r8-15,k8-15]
    const uint32_t a_loff = (uint32_t)(wm * ROW_B + (lid & 15) * ROW_B + (lid >> 4) * 16);
    // B x4 tiles: [n0-7,k0-7],[n0-7,k8-15],[n8-15,k0-7],[n8-15,k8-15]
    const uint32_t b_loff = (uint32_t)(A_STAGE_BYTES + wn * ROW_B + (lid & 7) * ROW_B
                                       + ((lid >> 3) & 1) * 16 + (lid >> 4) * (8 * ROW_B));

    // ---------------- stage loader ----------------
    // A: 128 rows x 8 chunks = 1024 (8/thread); B same.
    auto load_stage = [&](int buf, int k0) {
        __half* as_ = smemh + buf * STAGE_HALFS;
#pragma unroll
        for (int t = 0; t < 8; t++) {
            int idx = tid + t * NTHR;
            int r = idx >> 3, c = idx & 7;
            cp_async16(smem_to_u32(as_ + r * A_STRIDE_H + c * 8),
                       Ab + (size_t)r * lda + k0 + c * 8);
        }
        __half* bs_ = as_ + A_STAGE_HALFS;
#pragma unroll
        for (int t = 0; t < 8; t++) {
            int idx = tid + t * NTHR;
            int r = idx >> 3, c = idx & 7;
            cp_async16(smem_to_u32(bs_ + r * A_STRIDE_H + c * 8),
                       Bb + (size_t)r * ldb + k0 + c * 8);
        }
    };

    const int NK = K / KT;

    // prologue: fill stages 0..STAGES-2
#pragma unroll
    for (int s = 0; s < STAGES - 1; s++) {
        load_stage(s, s * KT);
        CP_ASYNC_COMMIT();
    }

    int buf = 0;
    for (int i = 0; i < NK; i++) {
        cp_async_wait_group<STAGES - 2>();
        __syncthreads();

        // issue next stage's loads into the buffer consumed last iteration
        const int jn = i + STAGES - 1;
        int nbuf = buf + 1; if (nbuf == STAGES) nbuf = 0;
        if (jn < NK) {
            int lbuf = buf - 1; if (lbuf < 0) lbuf += STAGES;
            load_stage(lbuf, jn * KT);
        }
        CP_ASYNC_COMMIT();

        // compute on stage `buf`: 4 k-slices of k16, 8 LDSM -> 32 MMA per slice
        const uint32_t sa = smem_base + buf * STAGE_BYTES;
#pragma unroll
        for (int kk = 0; kk < KT / 16; kk++) {
            const uint32_t koff = sa + kk * 32;
            uint32_t a[4][4];
#pragma unroll
            for (int f = 0; f < 4; f++)
                ldsm_x4(a[f], koff + a_loff + f * (16 * ROW_B));
            uint32_t bb[4][4];   // bb[p] = {j(2p).b0, j(2p).b1, j(2p+1).b0, j(2p+1).b1}
#pragma unroll
            for (int p = 0; p < 4; p++)
                ldsm_x4(bb[p], koff + b_loff + p * (16 * ROW_B));
#pragma unroll
            for (int f = 0; f < 4; f++)
#pragma unroll
                for (int j = 0; j < 8; j++)
                    mma_f16(acc[f][j], a[f],
                            bb[j >> 1][(j & 1) * 2], bb[j >> 1][(j & 1) * 2 + 1]);
        }
        buf = nbuf;
    }

    // ---------------- epilogue ----------------
    if (do_gelu) {
        __half* Cb = (__half*)Cv + (size_t)e * sCe + (size_t)mt * MT * ldc + (size_t)nt * NT;
#pragma unroll
        for (int f = 0; f < 4; f++) {
            const int r0 = wm + 16 * f + g;
            const int r1 = r0 + 8;
#pragma unroll
            for (int j = 0; j < 8; j++) {
                const int col = wn + 8 * j + 2 * tig;
                __half2 p0 = __floats2half2_rn(gelu_tanh(acc[f][j][0]),
                                               gelu_tanh(acc[f][j][1]));
                __half2 p1 = __floats2half2_rn(gelu_tanh(acc[f][j][2]),
                                               gelu_tanh(acc[f][j][3]));
                *reinterpret_cast<__half2*>(Cb + (size_t)r0 * ldc + col) = p0;
                *reinterpret_cast<__half2*>(Cb + (size_t)r1 * ldc + col) = p1;
            }
        }
    } else {
        float* Cb = (float*)Cv + (size_t)e * sCe + (size_t)mt * MT * ldc + (size_t)nt * NT;
#pragma unroll
        for (int f = 0; f < 4; f++) {
            const int r0 = wm + 16 * f + g;
            const int r1 = r0 + 8;
#pragma unroll
            for (int j = 0; j < 8; j++) {
                const int col = wn + 8 * j + 2 * tig;
                *reinterpret_cast<float2*>(Cb + (size_t)r0 * ldc + col) =
                    make_float2(acc[f][j][0], acc[f][j][1]);
                *reinterpret_cast<float2*>(Cb + (size_t)r1 * ldc + col) =
                    make_float2(acc[f][j][2], acc[f][j][3]);
            }
        }
    }
}

// ============================================================
// Host launcher
// ============================================================
extern "C" void kernel_launch(void* const* d_in, const int* in_sizes, int n_in,
                              void* d_out, int out_size)
{
    const float* x  = (const float*)d_in[0];
    const float* w1 = (const float*)d_in[1];
    const float* w2 = (const float*)d_in[2];
    float* out = (float*)d_out;

    __half *xh, *w1t, *w2t, *inter;
    cudaGetSymbolAddress((void**)&xh,    g_xh);
    cudaGetSymbolAddress((void**)&w1t,   g_w1t);
    cudaGetSymbolAddress((void**)&w2t,   g_w2t);
    cudaGetSymbolAddress((void**)&inter, g_inter);

    cudaFuncSetAttribute(gemm_f16_kernel,
                         cudaFuncAttributeMaxDynamicSharedMemorySize, SMEM_ALLOC);

    // prep: fp16 conversion + weight transposes to K-major
    convert_h_kernel<<<2048, 256>>>(x, xh, TOK_TOTAL * DIM_H);
    transpose_h_kernel<<<dim3(DIM_F / 32, DIM_H / 32, NUM_E), dim3(32, 8)>>>(
        w1, w1t, DIM_H, DIM_F);   // [E][H][F] -> [E][F][H]
    transpose_h_kernel<<<dim3(DIM_H / 32, DIM_F / 32, NUM_E), dim3(32, 8)>>>(
        w2, w2t, DIM_F, DIM_H);   // [E][F][H] -> [E][H][F]

    // GEMM1: inter = gelu(x @ w1^T_kmajor)   (M=2048/expert, N=4096, K=1024), fp16 out
    gemm_f16_kernel<<<dim3((TOK_PER_E / MT) * (DIM_F / NT), NUM_E), NTHR, SMEM_ALLOC>>>(
        xh,    DIM_H, (long)TOK_PER_E * DIM_H,
        w1t,   DIM_H, (long)DIM_F * DIM_H,
        inter, DIM_F, (long)TOK_PER_E * DIM_F,
        DIM_H, DIM_F / NT, /*gelu=*/1);

    // GEMM2: out = inter @ w2^T_kmajor       (M=2048/expert, N=1024, K=4096), fp32 out
    gemm_f16_kernel<<<dim3((TOK_PER_E / MT) * (DIM_H / NT), NUM_E), NTHR, SMEM_ALLOC>>>(
        inter, DIM_F, (long)TOK_PER_E * DIM_F,
        w2t,   DIM_F, (long)DIM_H * DIM_F,
        out,   DIM_H, (long)TOK_PER_E * DIM_H,
        DIM_F, DIM_H / NT, /*gelu=*/0);
}

// round 16
// speedup vs baseline: 1.1069x; 1.0389x over previous
#include <cuda_runtime.h>
#include <cuda_fp16.h>
#include <cstdint>

// ============================================================
// Problem constants
// ============================================================
#define NUM_E     8
#define DIM_H     1024
#define DIM_F     4096
#define TOK_TOTAL 16384
#define TOK_PER_E 2048

// GEMM tiling: CTA 128x128, 8 warps of 64x32, 3-stage pipeline, 2 CTA/SM
#define STAGES  3
#define KT      64             // k halves per stage (= 128 bytes/row)
#define MT      128
#define NT      128

#define A_STRIDE_H      72     // halves per smem row (64 data + 8 pad = 144B) -> conflict-free
#define ROW_B           144    // row bytes
#define A_STAGE_HALFS   (MT * A_STRIDE_H)        // 9216
#define B_STAGE_HALFS   (NT * A_STRIDE_H)        // 9216
#define STAGE_HALFS     (A_STAGE_HALFS + B_STAGE_HALFS)
#define STAGE_BYTES     (STAGE_HALFS * 2)        // 36864
#define A_STAGE_BYTES   (A_STAGE_HALFS * 2)      // 18432
#define SMEM_ALLOC      (STAGES * STAGE_BYTES)   // 110592 bytes

// ============================================================
// Scratch (__device__ globals — allocation-free rule)
// ============================================================
__device__ __half g_xh[(size_t)TOK_TOTAL * DIM_H];         //  32 MB  x (fp16)
__device__ __half g_w1t[(size_t)NUM_E * DIM_F * DIM_H];    //  64 MB  w1^T [e][f][h] fp16
__device__ __half g_w2t[(size_t)NUM_E * DIM_H * DIM_F];    //  64 MB  w2^T [e][h][f] fp16
__device__ __half g_inter[(size_t)TOK_TOTAL * DIM_F];      // 128 MB  gelu(x@w1) fp16

// ============================================================
// Helpers (baseline PTX only — no tcgen05 on this toolchain)
// ============================================================
__device__ __forceinline__ uint32_t smem_to_u32(const void* smem_ptr) {
    uint32_t addr;
    asm("{ .reg .u64 tmp; cvta.to.shared.u64 tmp, %1; cvt.u32.u64 %0, tmp; }"
        : "=r"(addr) : "l"(smem_ptr));
    return addr;
}

__device__ __forceinline__ void cp_async16(uint32_t smem_addr, const void* gptr) {
    asm volatile("cp.async.cg.shared.global [%0], [%1], 16;"
                 :: "r"(smem_addr), "l"(gptr));
}
#define CP_ASYNC_COMMIT() asm volatile("cp.async.commit_group;" ::: "memory")
template <int N>
__device__ __forceinline__ void cp_async_wait_group() {
    asm volatile("cp.async.wait_group %0;" :: "n"(N) : "memory");
}

// ldmatrix x4: four 8x8 b16 tiles
__device__ __forceinline__ void ldsm_x4(uint32_t (&d)[4], uint32_t addr) {
    asm volatile("ldmatrix.sync.aligned.m8n8.x4.shared.b16 {%0,%1,%2,%3}, [%4];"
                 : "=r"(d[0]), "=r"(d[1]), "=r"(d[2]), "=r"(d[3]) : "r"(addr));
}

// mma.sync m16n8k16 fp16 -> f32 accumulate (sm_80+ baseline PTX)
__device__ __forceinline__ void mma_f16(float (&d)[4],
                                        const uint32_t (&a)[4],
                                        uint32_t b0, uint32_t b1) {
    asm volatile(
        "mma.sync.aligned.m16n8k16.row.col.f32.f16.f16.f32 "
        "{%0,%1,%2,%3}, {%4,%5,%6,%7}, {%8,%9}, {%0,%1,%2,%3};"
        : "+f"(d[0]), "+f"(d[1]), "+f"(d[2]), "+f"(d[3])
        : "r"(a[0]), "r"(a[1]), "r"(a[2]), "r"(a[3]),
          "r"(b0), "r"(b1));
}

__device__ __forceinline__ float gelu_tanh(float x) {
    float x3 = x * x * x;
    float t  = tanhf(0.7978845608028654f * (x + 0.044715f * x3));
    return 0.5f * x * (1.0f + t);
}

// ============================================================
// Prep kernels: fp32 -> fp16 (RN), plus K-major transposes
// ============================================================
__global__ void convert_h_kernel(const float* __restrict__ in, __half* __restrict__ out, int n)
{
    for (int i = blockIdx.x * blockDim.x + threadIdx.x; i < n; i += gridDim.x * blockDim.x)
        out[i] = __float2half_rn(in[i]);
}

// in: [E][R][C] fp32 -> out: [E][C][R] fp16
__global__ void transpose_h_kernel(const float* __restrict__ in, __half* __restrict__ out,
                                   int R, int C)
{
    __shared__ float tile[32][33];
    const int e  = blockIdx.z;
    const int c0 = blockIdx.x << 5;
    const int r0 = blockIdx.y << 5;
    const float* ine  = in  + (size_t)e * R * C;
    __half*      oute = out + (size_t)e * R * C;
    const int tx = threadIdx.x, ty = threadIdx.y;   // 32 x 8
#pragma unroll
    for (int dy = 0; dy < 32; dy += 8)
        tile[ty + dy][tx] = ine[(size_t)(r0 + ty + dy) * C + c0 + tx];
    __syncthreads();
#pragma unroll
    for (int dy = 0; dy < 32; dy += 8)
        oute[(size_t)(c0 + ty + dy) * R + r0 + tx] = __float2half_rn(tile[tx][ty + dy]);
}

// ============================================================
// Grouped fp16 GEMM:  C[e] (+gelu) = A[e] @ B[e]^T
//   A: [Mtot, K] K-major fp16;  B: [Ntot, K] K-major fp16
//   C: fp16 (when do_gelu, -> inter) or fp32 (final output)
// CTA: 128x128, 8 warps of 64x32, KT=64, 3-stage cp.async, 2 CTA/SM,
// ldmatrix.x4 fragment loads + slice-level fragment double buffer.
// Stage sync order identical to r9 (wait -> syncthreads -> issue -> compute).
// ============================================================
__global__ void __launch_bounds__(256, 2) gemm_f16_kernel(
    const __half* __restrict__ A, int lda, long sAe,
    const __half* __restrict__ B, int ldb, long sBe,
    void* __restrict__ Cv, int ldc, long sCe,
    int K, int n_tiles, int do_gelu)
{
    extern __shared__ __half smemh[];
    const uint32_t smem_base = smem_to_u32(smemh);

    const int tid = threadIdx.x;
    const int wid = tid >> 5;
    const int lid = tid & 31;
    const int g   = lid >> 2;      // groupID (0..7)
    const int tig = lid & 3;       // thread in group (0..3)
    const int wm  = (wid & 1) * 64;      // 2 warps across M
    const int wn  = (wid >> 1) * 32;     // 4 warps across N

    const int e  = blockIdx.y;
    const int mt = blockIdx.x / n_tiles;
    const int nt = blockIdx.x - mt * n_tiles;

    const __half* Ab = A + (size_t)e * sAe + (size_t)mt * MT * lda;
    const __half* Bb = B + (size_t)e * sBe + (size_t)nt * NT * ldb;

    float acc[4][4][4];                  // [mfrag][nfrag][quad]
#pragma unroll
    for (int f = 0; f < 4; f++)
#pragma unroll
        for (int j = 0; j < 4; j++)
#pragma unroll
            for (int q = 0; q < 4; q++) acc[f][j][q] = 0.0f;

    // per-lane ldmatrix offsets (bytes, within a stage buffer):
    // A x4 tiles: [r0-7,k0-7],[r8-15,k0-7],[r0-7,k8-15],[r8-15,k8-15]
    const uint32_t a_loff = (uint32_t)(wm * ROW_B + (lid & 15) * ROW_B + (lid >> 4) * 16);
    // B x4 tiles: [n0-7,k0-7],[n0-7,k8-15],[n8-15,k0-7],[n8-15,k8-15]
    const uint32_t b_loff = (uint32_t)(A_STAGE_BYTES + wn * ROW_B + (lid & 7) * ROW_B
                                       + ((lid >> 3) & 1) * 16 + (lid >> 4) * (8 * ROW_B));

    // ---------------- stage loader ----------------
    // A: 128 rows x 128 bytes = 1024 16B chunks, 4/thread; B same.
    auto load_stage = [&](int buf, int k0) {
        __half* as_ = smemh + buf * STAGE_HALFS;
#pragma unroll
        for (int t = 0; t < 4; t++) {
            int idx = tid + t * 256;
            int r = idx >> 3, c = idx & 7;
            cp_async16(smem_to_u32(as_ + r * A_STRIDE_H + c * 8),
                       Ab + (size_t)r * lda + k0 + c * 8);
        }
        __half* bs_ = as_ + A_STAGE_HALFS;
#pragma unroll
        for (int t = 0; t < 4; t++) {
            int idx = tid + t * 256;
            int r = idx >> 3, c = idx & 7;
            cp_async16(smem_to_u32(bs_ + r * A_STRIDE_H + c * 8),
                       Bb + (size_t)r * ldb + k0 + c * 8);
        }
    };

    const int NK = K / KT;

    // prologue: fill stages 0..STAGES-2
#pragma unroll
    for (int s = 0; s < STAGES - 1; s++) {
        load_stage(s, s * KT);
        CP_ASYNC_COMMIT();
    }

    // fragment double buffers (slice-level software pipeline)
    uint32_t a[2][4][4];
    uint32_t bb[2][2][4];

    int buf = 0;
    for (int i = 0; i < NK; i++) {
        // wait for stage i's data, then barrier: makes all warps' data visible
        // AND proves everyone finished reading the buffer we overwrite next.
        cp_async_wait_group<STAGES - 2>();
        __syncthreads();

        // issue next stage's loads into the buffer consumed last iteration
        const int jn = i + STAGES - 1;
        int nbuf = buf + 1; if (nbuf == STAGES) nbuf = 0;
        if (jn < NK) {
            int lbuf = buf - 1; if (lbuf < 0) lbuf += STAGES;
            load_stage(lbuf, jn * KT);
        }
        CP_ASYNC_COMMIT();

        // compute on stage `buf`: 4 k-slices, frag-pipelined LDSM
        const uint32_t sa = smem_base + buf * STAGE_BYTES;

        // prime slice 0
#pragma unroll
        for (int f = 0; f < 4; f++)
            ldsm_x4(a[0][f], sa + a_loff + f * (16 * ROW_B));
#pragma unroll
        for (int p = 0; p < 2; p++)
            ldsm_x4(bb[0][p], sa + b_loff + p * (16 * ROW_B));

#pragma unroll
        for (int kk = 0; kk < KT / 16; kk++) {
            const int cur = kk & 1, nxt = cur ^ 1;
            if (kk < KT / 16 - 1) {
                const uint32_t koff = sa + (kk + 1) * 32;
#pragma unroll
                for (int f = 0; f < 4; f++)
                    ldsm_x4(a[nxt][f], koff + a_loff + f * (16 * ROW_B));
#pragma unroll
                for (int p = 0; p < 2; p++)
                    ldsm_x4(bb[nxt][p], koff + b_loff + p * (16 * ROW_B));
            }
#pragma unroll
            for (int f = 0; f < 4; f++)
#pragma unroll
                for (int j = 0; j < 4; j++)
                    mma_f16(acc[f][j], a[cur][f],
                            bb[cur][j >> 1][(j & 1) * 2], bb[cur][j >> 1][(j & 1) * 2 + 1]);
        }
        buf = nbuf;
    }

    // ---------------- epilogue ----------------
    if (do_gelu) {
        __half* Cb = (__half*)Cv + (size_t)e * sCe + (size_t)mt * MT * ldc + (size_t)nt * NT;
#pragma unroll
        for (int f = 0; f < 4; f++) {
            const int r0 = wm + 16 * f + g;
            const int r1 = r0 + 8;
#pragma unroll
            for (int j = 0; j < 4; j++) {
                const int col = wn + 8 * j + 2 * tig;
                __half2 p0 = __floats2half2_rn(gelu_tanh(acc[f][j][0]),
                                               gelu_tanh(acc[f][j][1]));
                __half2 p1 = __floats2half2_rn(gelu_tanh(acc[f][j][2]),
                                               gelu_tanh(acc[f][j][3]));
                *reinterpret_cast<__half2*>(Cb + (size_t)r0 * ldc + col) = p0;
                *reinterpret_cast<__half2*>(Cb + (size_t)r1 * ldc + col) = p1;
            }
        }
    } else {
        float* Cb = (float*)Cv + (size_t)e * sCe + (size_t)mt * MT * ldc + (size_t)nt * NT;
#pragma unroll
        for (int f = 0; f < 4; f++) {
            const int r0 = wm + 16 * f + g;
            const int r1 = r0 + 8;
#pragma unroll
            for (int j = 0; j < 4; j++) {
                const int col = wn + 8 * j + 2 * tig;
                *reinterpret_cast<float2*>(Cb + (size_t)r0 * ldc + col) =
                    make_float2(acc[f][j][0], acc[f][j][1]);
                *reinterpret_cast<float2*>(Cb + (size_t)r1 * ldc + col) =
                    make_float2(acc[f][j][2], acc[f][j][3]);
            }
        }
    }
}

// ============================================================
// Host launcher
// ============================================================
extern "C" void kernel_launch(void* const* d_in, const int* in_sizes, int n_in,
                              void* d_out, int out_size)
{
    const float* x  = (const float*)d_in[0];
    const float* w1 = (const float*)d_in[1];
    const float* w2 = (const float*)d_in[2];
    float* out = (float*)d_out;

    __half *xh, *w1t, *w2t, *inter;
    cudaGetSymbolAddress((void**)&xh,    g_xh);
    cudaGetSymbolAddress((void**)&w1t,   g_w1t);
    cudaGetSymbolAddress((void**)&w2t,   g_w2t);
    cudaGetSymbolAddress((void**)&inter, g_inter);

    cudaFuncSetAttribute(gemm_f16_kernel,
                         cudaFuncAttributeMaxDynamicSharedMemorySize, SMEM_ALLOC);

    // prep: fp16 conversion + weight transposes to K-major
    convert_h_kernel<<<2048, 256>>>(x, xh, TOK_TOTAL * DIM_H);
    transpose_h_kernel<<<dim3(DIM_F / 32, DIM_H / 32, NUM_E), dim3(32, 8)>>>(
        w1, w1t, DIM_H, DIM_F);   // [E][H][F] -> [E][F][H]
    transpose_h_kernel<<<dim3(DIM_H / 32, DIM_F / 32, NUM_E), dim3(32, 8)>>>(
        w2, w2t, DIM_F, DIM_H);   // [E][F][H] -> [E][H][F]

    // GEMM1: inter = gelu(x @ w1^T_kmajor)   (M=2048/expert, N=4096, K=1024), fp16 out
    gemm_f16_kernel<<<dim3((TOK_PER_E / MT) * (DIM_F / NT), NUM_E), 256, SMEM_ALLOC>>>(
        xh,    DIM_H, (long)TOK_PER_E * DIM_H,
        w1t,   DIM_H, (long)DIM_F * DIM_H,
        inter, DIM_F, (long)TOK_PER_E * DIM_F,
        DIM_H, DIM_F / NT, /*gelu=*/1);

    // GEMM2: out = inter @ w2^T_kmajor       (M=2048/expert, N=1024, K=4096), fp32 out
    gemm_f16_kernel<<<dim3((TOK_PER_E / MT) * (DIM_H / NT), NUM_E), 256, SMEM_ALLOC>>>(
        inter, DIM_F, (long)TOK_PER_E * DIM_F,
        w2t,   DIM_F, (long)DIM_H * DIM_F,
        out,   DIM_H, (long)TOK_PER_E * DIM_H,
        DIM_F, DIM_H / NT, /*gelu=*/0);
}